// round 12
// baseline (speedup 1.0000x reference)
#include <cuda_runtime.h>
#include <cuda_fp16.h>

#define NN 100000
#define NNP 100096          // padded to 128-node k2 blocks (782 * 128)
#define NE 1600000
#define NBUK 98             // col buckets of 1024 nodes
#define CSPLIT 50176        // 392 * 128 node split for k2a/k2b + k3a/k3b

// fp16 copy of x
__device__ __half g_xh[(size_t)NNP * 32];
// xw' (PERMUTED feature layout) fp16: [NNP][25 kernels][64B]
__device__ uint2 g_xwp[(size_t)NNP * 200];
__device__ float g_att2p[32];                // attW[32..64) permuted
__device__ float g_biasp[32];                // bias permuted
__device__ float g_acc[(size_t)NN * 32];     // permuted space
__device__ float g_xrb[(size_t)NNP * 32];    // x_root, PERMUTED fp32 (from k2)
__device__ float g_rdot[NNP];
__device__ float g_denom[NN];
// edge bucketing (g_bcnt is zero at entry; k4 restores the invariant)
__device__ int   g_bcnt[NBUK];
__device__ int   g_bcur[NBUK];
__device__ uint4 g_rec[NE];                  // {row, col, pseudo.x, pseudo.y}

__device__ __forceinline__ unsigned h2b(float a, float b) {
    unsigned r; asm("cvt.rn.f16x2.f32 %0,%2,%1;" : "=r"(r) : "f"(a), "f"(b));
    return r;   // low half = a
}
__device__ __forceinline__ unsigned sm_u32(const void* p) {
    unsigned r;
    asm("{.reg .u64 t; cvta.to.shared.u64 t, %1; cvt.u32.u64 %0, t;}"
        : "=r"(r) : "l"(p));
    return r;
}
__device__ __forceinline__ void ldsm4(unsigned& r0, unsigned& r1,
                                      unsigned& r2, unsigned& r3, unsigned a) {
    asm volatile("ldmatrix.sync.aligned.m8n8.x4.shared.b16 {%0,%1,%2,%3}, [%4];"
                 : "=r"(r0), "=r"(r1), "=r"(r2), "=r"(r3) : "r"(a));
}
__device__ __forceinline__ void ldsm4t(unsigned& r0, unsigned& r1,
                                       unsigned& r2, unsigned& r3, unsigned a) {
    asm volatile("ldmatrix.sync.aligned.m8n8.x4.trans.shared.b16 {%0,%1,%2,%3}, [%4];"
                 : "=r"(r0), "=r"(r1), "=r"(r2), "=r"(r3) : "r"(a));
}
__device__ __forceinline__ void mma16816(float* c, const unsigned* a,
                                         unsigned b0, unsigned b1) {
    asm volatile("mma.sync.aligned.m16n8k16.row.col.f32.f16.f16.f32 "
                 "{%0,%1,%2,%3}, {%4,%5,%6,%7}, {%8,%9}, {%0,%1,%2,%3};"
                 : "+f"(c[0]), "+f"(c[1]), "+f"(c[2]), "+f"(c[3])
                 : "r"(a[0]), "r"(a[1]), "r"(a[2]), "r"(a[3]), "r"(b0), "r"(b1));
}

// ---------------------------------------------------------------------------
// S1: per-bucket histogram of col (smem-staged). g_bcnt is 0 at entry.
// ---------------------------------------------------------------------------
__global__ __launch_bounds__(256) void s1_hist(const int* __restrict__ ei)
{
    __shared__ int h[NBUK];
    int tid = threadIdx.x;
    if (tid < NBUK) h[tid] = 0;
    __syncthreads();
    int base = blockIdx.x * 2560;          // 625 blocks * 2560 = NE
#pragma unroll
    for (int i = 0; i < 10; i++) {
        int col = __ldg(ei + NE + base + i * 256 + tid);
        atomicAdd(&h[col >> 10], 1);
    }
    __syncthreads();
    if (tid < NBUK) atomicAdd(&g_bcnt[tid], h[tid]);
}

// ---------------------------------------------------------------------------
// S2: exclusive scan of bucket counts + permuted att2/bias tables
// ---------------------------------------------------------------------------
__global__ void s2_scan(const float* __restrict__ attW,
                        const float* __restrict__ bias)
{
    int i = threadIdx.x;                 // 128 threads
    if (i == 0) {
        int s = 0;
        for (int b = 0; b < NBUK; b++) { int c = g_bcnt[b]; g_bcur[b] = s; s += c; }
    }
    if (i < 32) {
        int sub = i >> 2, j = i & 3;
        int c = sub >> 1, h = sub & 1;
        int f = 16 * h + 8 * (j >> 1) + 2 * c + (j & 1);
        g_att2p[i] = attW[32 + f];
        g_biasp[i] = bias[f];
    }
}

// ---------------------------------------------------------------------------
// S3: scatter edges into bucket-ordered record array (block-staged)
// ---------------------------------------------------------------------------
__global__ __launch_bounds__(256) void s3_scat(
    const int* __restrict__ ei, const float* __restrict__ pseudo)
{
    __shared__ int h[NBUK], st[NBUK];
    int tid = threadIdx.x;
    if (tid < NBUK) h[tid] = 0;
    __syncthreads();
    int base = blockIdx.x * 2560;
    int myrow[10], mycol[10];
    float2 myps[10];
#pragma unroll
    for (int i = 0; i < 10; i++) {
        int e = base + i * 256 + tid;
        myrow[i] = __ldg(ei + e);
        mycol[i] = __ldg(ei + NE + e);
        myps[i]  = __ldg((const float2*)pseudo + e);
        atomicAdd(&h[mycol[i] >> 10], 1);
    }
    __syncthreads();
    if (tid < NBUK) st[tid] = atomicAdd(&g_bcur[tid], h[tid]);
    __syncthreads();
    if (tid < NBUK) h[tid] = 0;
    __syncthreads();
#pragma unroll
    for (int i = 0; i < 10; i++) {
        int b = mycol[i] >> 10;
        int pos = st[b] + atomicAdd(&h[b], 1);
        g_rec[pos] = make_uint4((unsigned)myrow[i], (unsigned)mycol[i],
                                __float_as_uint(myps[i].x),
                                __float_as_uint(myps[i].y));
    }
}

// ---------------------------------------------------------------------------
// K1: x -> fp16 copy + rdot (x . (rootW @ att1), fp32) + zero acc/denom
// ---------------------------------------------------------------------------
__global__ __launch_bounds__(256) void k1_conv(
    const float* __restrict__ x, const float* __restrict__ rootW,
    const float* __restrict__ attW)
{
    __shared__ float vsh[32];
    int tid = threadIdx.x;
    if (tid < 32) {
        const float* rw = rootW + tid * 32;
        float s = 0.f;
#pragma unroll
        for (int o = 0; o < 32; o++) s += __ldg(rw + o) * __ldg(attW + o);
        vsh[tid] = s;
    }
    __syncthreads();

    int n = blockIdx.x * 256 + tid;
    if (n >= NN) return;
    const float4* xp = (const float4*)(x + (size_t)n * 32);
    uint4* xhp = ((uint4*)g_xh) + (size_t)n * 4;
    float rd = 0.f;
#pragma unroll
    for (int j = 0; j < 4; j++) {
        float4 t0 = xp[2*j], t1 = xp[2*j+1];
        uint4 h;
        h.x = h2b(t0.x, t0.y); h.y = h2b(t0.z, t0.w);
        h.z = h2b(t1.x, t1.y); h.w = h2b(t1.z, t1.w);
        xhp[j] = h;
        rd += t0.x * vsh[8*j]   + t0.y * vsh[8*j+1]
            + t0.z * vsh[8*j+2] + t0.w * vsh[8*j+3]
            + t1.x * vsh[8*j+4] + t1.y * vsh[8*j+5]
            + t1.z * vsh[8*j+6] + t1.w * vsh[8*j+7];
    }
    g_rdot[n] = rd;
    float4* accp = (float4*)(g_acc + (size_t)n * 32);
#pragma unroll
    for (int j = 0; j < 8; j++)
        accp[j] = make_float4(0.f, 0.f, 0.f, 0.f);
    g_denom[n] = 0.f;
}

// ---------------------------------------------------------------------------
// K2: raw mma.m16n8k16, 26 kernels (25 spline + root), node-range chunk.
// ---------------------------------------------------------------------------
__global__ __launch_bounds__(256) void k2_mma(
    const float* __restrict__ W, const float* __restrict__ rootW, int n0base)
{
    extern __shared__ __align__(16) char smraw[];
    uint4* Wd = (uint4*)smraw;                 // 3328 uint4 (26 * 2048B)
    uint4* Ad = (uint4*)(smraw + 53248);       // 512 uint4

    int tid = threadIdx.x;
    int blk0 = n0base + blockIdx.x * 128;
    {
#pragma unroll
        for (int i = 0; i < 13; i++) {
            int ch = tid + 256 * i;            // 3328 exact
            int kk = ch >> 7, r = (ch >> 2) & 31, c = ch & 3;
            const float* src = (kk < 25 ? W + kk * 1024 : rootW) + r * 32 + c * 8;
            float4 s0 = __ldg((const float4*)src);
            float4 s1 = __ldg((const float4*)src + 1);
            uint4 v;
            v.x = h2b(s0.x, s0.y); v.y = h2b(s0.z, s0.w);
            v.z = h2b(s1.x, s1.y); v.w = h2b(s1.z, s1.w);
            Wd[kk * 128 + r * 4 + (c ^ ((r >> 1) & 3))] = v;
        }
        const uint4* xsrc = ((const uint4*)g_xh) + (size_t)blk0 * 4;
#pragma unroll
        for (int i = 0; i < 2; i++) {
            int ch = tid + 256 * i;
            int nd = ch >> 2, c = ch & 3;
            Ad[nd * 4 + (c ^ ((nd >> 1) & 3))] = xsrc[ch];
        }
    }
    __syncthreads();

    int lane = tid & 31, warp = tid >> 5;
    int n0 = warp * 16;
    unsigned Ab = sm_u32(Ad), Wb = sm_u32(Wd);

    int Lr = lane & 7, mg = lane >> 3;
    int anode = n0 + Lr + 8 * (mg & 1);
    int acb = mg >> 1;
    unsigned A0[4], A1[4];
    ldsm4(A0[0], A0[1], A0[2], A0[3],
          Ab + anode * 64 + (((acb)     ^ ((anode >> 1) & 3)) << 4));
    ldsm4(A1[0], A1[1], A1[2], A1[3],
          Ab + anode * 64 + (((acb + 2) ^ ((anode >> 1) & 3)) << 4));

    unsigned wrow = Wb + lane * 64;
    unsigned bsw0 = ((0 ^ ((lane >> 1) & 3)) << 4);
    unsigned bsw1 = ((1 ^ ((lane >> 1) & 3)) << 4);
    unsigned bsw2 = ((2 ^ ((lane >> 1) & 3)) << 4);
    unsigned bsw3 = ((3 ^ ((lane >> 1) & 3)) << 4);

    int node = blk0 + n0 + (lane >> 2);
    char* outb = ((char*)g_xwp) + (size_t)node * 1600 + (lane & 3) * 16;

#pragma unroll 1
    for (int k = 0; k < 25; k++) {
        unsigned wk = wrow + k * 2048;
        float c0[4] = {0,0,0,0}, c1[4] = {0,0,0,0};
        float c2[4] = {0,0,0,0}, c3[4] = {0,0,0,0};
        unsigned b0, b1, b2, b3;
        ldsm4t(b0, b1, b2, b3, wk + bsw0);
        mma16816(c0, A0, b0, b1); mma16816(c0, A1, b2, b3);
        ldsm4t(b0, b1, b2, b3, wk + bsw1);
        mma16816(c1, A0, b0, b1); mma16816(c1, A1, b2, b3);
        ldsm4t(b0, b1, b2, b3, wk + bsw2);
        mma16816(c2, A0, b0, b1); mma16816(c2, A1, b2, b3);
        ldsm4t(b0, b1, b2, b3, wk + bsw3);
        mma16816(c3, A0, b0, b1); mma16816(c3, A1, b2, b3);

        uint4 v0, v1;
        v0.x = h2b(c0[0], c0[1]); v0.y = h2b(c1[0], c1[1]);
        v0.z = h2b(c2[0], c2[1]); v0.w = h2b(c3[0], c3[1]);
        v1.x = h2b(c0[2], c0[3]); v1.y = h2b(c1[2], c1[3]);
        v1.z = h2b(c2[2], c2[3]); v1.w = h2b(c3[2], c3[3]);
        *(uint4*)(outb + k * 64) = v0;                   // row r
        *(uint4*)(outb + k * 64 + 8 * 1600) = v1;        // row r+8
    }

    // k = 25: root transform (fp32 permuted)
    {
        unsigned wk = wrow + 25 * 2048;
        float c0[4] = {0,0,0,0}, c1[4] = {0,0,0,0};
        float c2[4] = {0,0,0,0}, c3[4] = {0,0,0,0};
        unsigned b0, b1, b2, b3;
        ldsm4t(b0, b1, b2, b3, wk + bsw0);
        mma16816(c0, A0, b0, b1); mma16816(c0, A1, b2, b3);
        ldsm4t(b0, b1, b2, b3, wk + bsw1);
        mma16816(c1, A0, b0, b1); mma16816(c1, A1, b2, b3);
        ldsm4t(b0, b1, b2, b3, wk + bsw2);
        mma16816(c2, A0, b0, b1); mma16816(c2, A1, b2, b3);
        ldsm4t(b0, b1, b2, b3, wk + bsw3);
        mma16816(c3, A0, b0, b1); mma16816(c3, A1, b2, b3);

        float* xo = g_xrb + (size_t)node * 32 + (lane & 3) * 8;
        *(float4*)(xo)       = make_float4(c0[0], c0[1], c1[0], c1[1]);
        *(float4*)(xo + 4)   = make_float4(c2[0], c2[1], c3[0], c3[1]);
        *(float4*)(xo + 256) = make_float4(c0[2], c0[3], c1[2], c1[3]);
        *(float4*)(xo + 260) = make_float4(c2[2], c2[3], c3[2], c3[3]);
    }
}

// ---------------------------------------------------------------------------
// K3: bucket-ordered edge pass over cols in [lo, hi). 8 lanes/edge.
//   Early-exit per 8-lane group -> all shuffles use group-local masks.
// ---------------------------------------------------------------------------
__global__ __launch_bounds__(256) void k3_edge(unsigned lo, unsigned hi)
{
    int t = blockIdx.x * 256 + threadIdx.x;
    int j   = t >> 3;
    int sub = t & 7;

    uint4 rc = __ldg(g_rec + j);
    unsigned col = rc.y;
    if (col - lo >= hi - lo) return;           // group-uniform exit
    int row = (int)rc.x;
    float p0 = __uint_as_float(rc.z) * 4.f;
    float p1 = __uint_as_float(rc.w) * 4.f;
    float fl0 = floorf(p0), fl1 = floorf(p1);
    float fr0 = p0 - fl0,   fr1 = p1 - fl1;
    int w0 = (int)fl0 + 5 * (int)fl1;

    const char* basep = (const char*)g_xwp + (size_t)col * 1600 + (sub << 4);
    uint4 qa = __ldg((const uint4*)(basep + w0 * 64));          // taps (0,0)/(1,0)
    uint4 qb = __ldg((const uint4*)(basep + (w0 + 5) * 64));    // taps (0,1)/(1,1)

    unsigned gm = 0xFFu << (threadIdx.x & 24);  // 8-lane group mask

    float fa = (sub & 4) ? fr0 : (1.f - fr0);
    unsigned ua = h2b(fa * (1.f - fr1), fa * (1.f - fr1));
    unsigned ub = h2b(fa * fr1,         fa * fr1);
    __half2 ha = *(__half2*)&ua, hb = *(__half2*)&ub;

    __half2 h0 = __hmul2(ha, *(__half2*)&qa.x);
    __half2 h1 = __hmul2(ha, *(__half2*)&qa.y);
    __half2 h2 = __hmul2(ha, *(__half2*)&qa.z);
    __half2 h3 = __hmul2(ha, *(__half2*)&qa.w);
    h0 = __hfma2(hb, *(__half2*)&qb.x, h0);
    h1 = __hfma2(hb, *(__half2*)&qb.y, h1);
    h2 = __hfma2(hb, *(__half2*)&qb.z, h2);
    h3 = __hfma2(hb, *(__half2*)&qb.w, h3);

    unsigned uu;
    uu = __shfl_xor_sync(gm, *(unsigned*)&h0, 4);
    h0 = __hadd2(h0, *(__half2*)&uu);
    uu = __shfl_xor_sync(gm, *(unsigned*)&h1, 4);
    h1 = __hadd2(h1, *(__half2*)&uu);
    uu = __shfl_xor_sync(gm, *(unsigned*)&h2, 4);
    h2 = __hadd2(h2, *(__half2*)&uu);
    uu = __shfl_xor_sync(gm, *(unsigned*)&h3, 4);
    h3 = __hadd2(h3, *(__half2*)&uu);

    float2 f0 = __half22float2(h0), f1 = __half22float2(h1);
    float2 f2 = __half22float2(h2), f3 = __half22float2(h3);

    int s = sub & 3;
    float4 A0 = __ldg(((const float4*)g_att2p) + 2 * s);
    float4 A1 = __ldg(((const float4*)g_att2p) + 2 * s + 1);
    float d = f0.x*A0.x + f0.y*A0.y + f1.x*A0.z + f1.y*A0.w
            + f2.x*A1.x + f2.y*A1.y + f3.x*A1.z + f3.y*A1.w;
    d += __shfl_xor_sync(gm, d, 1);
    d += __shfl_xor_sync(gm, d, 2);

    float alpha = d + __ldg(g_rdot + row);
    alpha = (alpha > 0.f) ? alpha : 0.2f * alpha;    // leaky relu
    float ex = __expf(alpha);       // softmax max-shift cancels in the ratio

    if (sub == 0) atomicAdd(g_denom + row, ex);

    float* ap = g_acc + (size_t)row * 32 + s * 8 + (sub & 4);
    float4 wv = (sub & 4)
        ? make_float4(f2.x * ex, f2.y * ex, f3.x * ex, f3.y * ex)
        : make_float4(f0.x * ex, f0.y * ex, f1.x * ex, f1.y * ex);
    asm volatile("red.global.add.v4.f32 [%0], {%1,%2,%3,%4};"
                 :: "l"(ap), "f"(wv.x), "f"(wv.y), "f"(wv.z), "f"(wv.w)
                 : "memory");
}

// ---------------------------------------------------------------------------
// K4: out = unpermute( acc/(denom+1e-16) + x_root_perm + bias_perm )
//     + restore g_bcnt=0 invariant for the next launch
// ---------------------------------------------------------------------------
__global__ __launch_bounds__(256) void k4_out(float* __restrict__ out)
{
    if (blockIdx.x == 0 && threadIdx.x < NBUK) g_bcnt[threadIdx.x] = 0;

    int i = blockIdx.x * 256 + threadIdx.x;     // 800000 = NN*8
    int n = i >> 3, g = i & 7;
    float r = 1.f / (g_denom[n] + 1e-16f);
    const float* ap  = g_acc + (size_t)n * 32;
    const float* xp_ = g_xrb + (size_t)n * 32;
    int h  = (g >> 2) & 1;
    int bb = (g >> 1) & 1;
    int pos0 = 8 * ((2 * g) & 3)     + 4 * h + 2 * bb;
    int pos1 = 8 * ((2 * g + 1) & 3) + 4 * h + 2 * bb;
    float2 u0 = *(const float2*)(ap + pos0);
    float2 u1 = *(const float2*)(ap + pos1);
    float2 x0 = *(const float2*)(xp_ + pos0);
    float2 x1 = *(const float2*)(xp_ + pos1);
    float2 b0 = *(const float2*)(g_biasp + pos0);
    float2 b1 = *(const float2*)(g_biasp + pos1);
    float4 o;
    o.x = fmaf(u0.x, r, x0.x + b0.x);
    o.y = fmaf(u0.y, r, x0.y + b0.y);
    o.z = fmaf(u1.x, r, x1.x + b1.x);
    o.w = fmaf(u1.y, r, x1.y + b1.y);
    ((float4*)out)[i] = o;
}

extern "C" void kernel_launch(void* const* d_in, const int* in_sizes, int n_in,
                              void* d_out, int out_size)
{
    const float* x      = (const float*)d_in[0];
    const int*   ei     = (const int*)d_in[1];
    const float* pseudo = (const float*)d_in[2];
    const float* W      = (const float*)d_in[3];
    const float* rootW  = (const float*)d_in[4];
    const float* attW   = (const float*)d_in[5];
    const float* bias   = (const float*)d_in[6];
    float* out = (float*)d_out;

    static cudaStream_t s_side = nullptr;
    static cudaEvent_t evF = nullptr, evS = nullptr, evA = nullptr, ev3a = nullptr;
    if (!s_side) {
        cudaFuncSetAttribute(k2_mma,
            cudaFuncAttributeMaxDynamicSharedMemorySize, 61440);
        cudaStreamCreateWithFlags(&s_side, cudaStreamNonBlocking);
        cudaEventCreateWithFlags(&evF, cudaEventDisableTiming);
        cudaEventCreateWithFlags(&evS, cudaEventDisableTiming);
        cudaEventCreateWithFlags(&evA, cudaEventDisableTiming);
        cudaEventCreateWithFlags(&ev3a, cudaEventDisableTiming);
    }

    // fork: sort chain + tables on side stream (depends only on ei/pseudo/attW/bias)
    cudaEventRecord(evF, 0);
    cudaStreamWaitEvent(s_side, evF, 0);
    s1_hist<<<625, 256, 0, s_side>>>(ei);
    s2_scan<<<1, 128, 0, s_side>>>(attW, bias);
    s3_scat<<<625, 256, 0, s_side>>>(ei, pseudo);
    cudaEventRecord(evS, s_side);

    // main chain: node-side work
    k1_conv<<<(NN + 255) / 256, 256>>>(x, rootW, attW);
    k2_mma <<<CSPLIT / 128, 256, 61440>>>(W, rootW, 0);
    cudaEventRecord(evA, 0);

    // side stream: k3a (low-col edges) overlaps k2b
    cudaStreamWaitEvent(s_side, evA, 0);
    k3_edge<<<(NE * 8) / 256, 256, 0, s_side>>>(0u, (unsigned)CSPLIT);
    cudaEventRecord(ev3a, s_side);

    // main: second node chunk, then high-col edges
    k2_mma <<<(NNP - CSPLIT) / 128, 256, 61440>>>(W, rootW, CSPLIT);
    cudaStreamWaitEvent(0, evS, 0);
    k3_edge<<<(NE * 8) / 256, 256>>>( (unsigned)CSPLIT, 0xFFFFFFFFu);

    // join and epilogue
    cudaStreamWaitEvent(0, ev3a, 0);
    k4_out <<<3125, 256>>>(out);
}

// round 13
// speedup vs baseline: 1.2174x; 1.2174x over previous
#include <cuda_runtime.h>
#include <cuda_fp16.h>

#define NN 100000
#define NNP 100096          // padded to 128-node k2 blocks (782 * 128)
#define NE 1600000
#define NBUK 98             // col buckets of 1024 nodes

// fp16 copy of x
__device__ __half g_xh[(size_t)NNP * 32];
// xw' (PERMUTED feature layout) fp16: [NNP][25 kernels][64B]
__device__ uint2 g_xwp[(size_t)NNP * 200];
__device__ float g_att2p[32];                // attW[32..64) permuted
__device__ float g_biasp[32];                // bias permuted
__device__ float g_acc[(size_t)NN * 32];     // permuted space
__device__ float g_xrb[(size_t)NNP * 32];    // x_root, PERMUTED fp32 (from k2)
__device__ float g_rdot[NNP];
__device__ float g_denom[NN];
// edge bucketing (g_bcnt is zero at entry; k4 restores the invariant)
__device__ int   g_bcnt[NBUK];
__device__ int   g_bcur[NBUK];
__device__ uint4 g_rec[NE];                  // {row, col, pseudo.x, pseudo.y}

__device__ __forceinline__ unsigned h2b(float a, float b) {
    unsigned r; asm("cvt.rn.f16x2.f32 %0,%2,%1;" : "=r"(r) : "f"(a), "f"(b));
    return r;   // low half = a
}
__device__ __forceinline__ unsigned sm_u32(const void* p) {
    unsigned r;
    asm("{.reg .u64 t; cvta.to.shared.u64 t, %1; cvt.u32.u64 %0, t;}"
        : "=r"(r) : "l"(p));
    return r;
}
__device__ __forceinline__ void ldsm4(unsigned& r0, unsigned& r1,
                                      unsigned& r2, unsigned& r3, unsigned a) {
    asm volatile("ldmatrix.sync.aligned.m8n8.x4.shared.b16 {%0,%1,%2,%3}, [%4];"
                 : "=r"(r0), "=r"(r1), "=r"(r2), "=r"(r3) : "r"(a));
}
__device__ __forceinline__ void ldsm4t(unsigned& r0, unsigned& r1,
                                       unsigned& r2, unsigned& r3, unsigned a) {
    asm volatile("ldmatrix.sync.aligned.m8n8.x4.trans.shared.b16 {%0,%1,%2,%3}, [%4];"
                 : "=r"(r0), "=r"(r1), "=r"(r2), "=r"(r3) : "r"(a));
}
__device__ __forceinline__ void mma16816(float* c, const unsigned* a,
                                         unsigned b0, unsigned b1) {
    asm volatile("mma.sync.aligned.m16n8k16.row.col.f32.f16.f16.f32 "
                 "{%0,%1,%2,%3}, {%4,%5,%6,%7}, {%8,%9}, {%0,%1,%2,%3};"
                 : "+f"(c[0]), "+f"(c[1]), "+f"(c[2]), "+f"(c[3])
                 : "r"(a[0]), "r"(a[1]), "r"(a[2]), "r"(a[3]), "r"(b0), "r"(b1));
}

// ---------------------------------------------------------------------------
// S1: per-bucket histogram of col (smem-staged). g_bcnt is 0 at entry.
// ---------------------------------------------------------------------------
__global__ __launch_bounds__(256) void s1_hist(const int* __restrict__ ei)
{
    __shared__ int h[NBUK];
    int tid = threadIdx.x;
    if (tid < NBUK) h[tid] = 0;
    __syncthreads();
    int base = blockIdx.x * 2560;          // 625 blocks * 2560 = NE
#pragma unroll
    for (int i = 0; i < 10; i++) {
        int col = __ldg(ei + NE + base + i * 256 + tid);
        atomicAdd(&h[col >> 10], 1);
    }
    __syncthreads();
    if (tid < NBUK) atomicAdd(&g_bcnt[tid], h[tid]);
}

// ---------------------------------------------------------------------------
// S2: exclusive scan of bucket counts + permuted att2/bias tables
//     (tables consumed only by k3/k4, which are ordered after this via evJ)
// ---------------------------------------------------------------------------
__global__ void s2_scan(const float* __restrict__ attW,
                        const float* __restrict__ bias)
{
    int i = threadIdx.x;                 // 128 threads
    if (i == 0) {
        int s = 0;
        for (int b = 0; b < NBUK; b++) { int c = g_bcnt[b]; g_bcur[b] = s; s += c; }
    }
    if (i < 32) {
        int sub = i >> 2, j = i & 3;
        int c = sub >> 1, h = sub & 1;
        int f = 16 * h + 8 * (j >> 1) + 2 * c + (j & 1);
        g_att2p[i] = attW[32 + f];
        g_biasp[i] = bias[f];
    }
}

// ---------------------------------------------------------------------------
// S3: scatter edges into bucket-ordered record array (block-staged)
// ---------------------------------------------------------------------------
__global__ __launch_bounds__(256) void s3_scat(
    const int* __restrict__ ei, const float* __restrict__ pseudo)
{
    __shared__ int h[NBUK], st[NBUK];
    int tid = threadIdx.x;
    if (tid < NBUK) h[tid] = 0;
    __syncthreads();
    int base = blockIdx.x * 2560;
    int myrow[10], mycol[10];
    float2 myps[10];
#pragma unroll
    for (int i = 0; i < 10; i++) {
        int e = base + i * 256 + tid;
        myrow[i] = __ldg(ei + e);
        mycol[i] = __ldg(ei + NE + e);
        myps[i]  = __ldg((const float2*)pseudo + e);
        atomicAdd(&h[mycol[i] >> 10], 1);
    }
    __syncthreads();
    if (tid < NBUK) st[tid] = atomicAdd(&g_bcur[tid], h[tid]);
    __syncthreads();
    if (tid < NBUK) h[tid] = 0;
    __syncthreads();
#pragma unroll
    for (int i = 0; i < 10; i++) {
        int b = mycol[i] >> 10;
        int pos = st[b] + atomicAdd(&h[b], 1);
        g_rec[pos] = make_uint4((unsigned)myrow[i], (unsigned)mycol[i],
                                __float_as_uint(myps[i].x),
                                __float_as_uint(myps[i].y));
    }
}

// ---------------------------------------------------------------------------
// K1: x -> fp16 copy + zero acc/denom
// ---------------------------------------------------------------------------
__global__ __launch_bounds__(256) void k1_conv(const float* __restrict__ x)
{
    int n = blockIdx.x * 256 + threadIdx.x;
    if (n >= NN) return;
    const float4* xp = (const float4*)(x + (size_t)n * 32);
    uint4* xhp = ((uint4*)g_xh) + (size_t)n * 4;
#pragma unroll
    for (int j = 0; j < 4; j++) {
        float4 t0 = xp[2*j], t1 = xp[2*j+1];
        uint4 h;
        h.x = h2b(t0.x, t0.y); h.y = h2b(t0.z, t0.w);
        h.z = h2b(t1.x, t1.y); h.w = h2b(t1.z, t1.w);
        xhp[j] = h;
    }
    float4* accp = (float4*)(g_acc + (size_t)n * 32);
#pragma unroll
    for (int j = 0; j < 8; j++)
        accp[j] = make_float4(0.f, 0.f, 0.f, 0.f);
    g_denom[n] = 0.f;
}

// ---------------------------------------------------------------------------
// K2: raw mma.m16n8k16, 26 kernels (25 spline + root).
//   rdot epilogue reads attW directly (permutation folded into addressing).
// ---------------------------------------------------------------------------
__global__ __launch_bounds__(256) void k2_mma(
    const float* __restrict__ W, const float* __restrict__ rootW,
    const float* __restrict__ attW)
{
    extern __shared__ __align__(16) char smraw[];
    uint4* Wd = (uint4*)smraw;                 // 3328 uint4 (26 * 2048B)
    uint4* Ad = (uint4*)(smraw + 53248);       // 512 uint4

    int tid = threadIdx.x;
    {
#pragma unroll
        for (int i = 0; i < 13; i++) {
            int ch = tid + 256 * i;            // 3328 exact
            int kk = ch >> 7, r = (ch >> 2) & 31, c = ch & 3;
            const float* src = (kk < 25 ? W + kk * 1024 : rootW) + r * 32 + c * 8;
            float4 s0 = __ldg((const float4*)src);
            float4 s1 = __ldg((const float4*)src + 1);
            uint4 v;
            v.x = h2b(s0.x, s0.y); v.y = h2b(s0.z, s0.w);
            v.z = h2b(s1.x, s1.y); v.w = h2b(s1.z, s1.w);
            Wd[kk * 128 + r * 4 + (c ^ ((r >> 1) & 3))] = v;
        }
        int n0g = blockIdx.x * 128;
        const uint4* xsrc = ((const uint4*)g_xh) + (size_t)n0g * 4;
#pragma unroll
        for (int i = 0; i < 2; i++) {
            int ch = tid + 256 * i;
            int nd = ch >> 2, c = ch & 3;
            Ad[nd * 4 + (c ^ ((nd >> 1) & 3))] = xsrc[ch];
        }
    }
    __syncthreads();

    int lane = tid & 31, warp = tid >> 5;
    int n0 = warp * 16;
    unsigned Ab = sm_u32(Ad), Wb = sm_u32(Wd);

    int Lr = lane & 7, mg = lane >> 3;
    int anode = n0 + Lr + 8 * (mg & 1);
    int acb = mg >> 1;
    unsigned A0[4], A1[4];
    ldsm4(A0[0], A0[1], A0[2], A0[3],
          Ab + anode * 64 + (((acb)     ^ ((anode >> 1) & 3)) << 4));
    ldsm4(A1[0], A1[1], A1[2], A1[3],
          Ab + anode * 64 + (((acb + 2) ^ ((anode >> 1) & 3)) << 4));

    unsigned wrow = Wb + lane * 64;
    unsigned bsw0 = ((0 ^ ((lane >> 1) & 3)) << 4);
    unsigned bsw1 = ((1 ^ ((lane >> 1) & 3)) << 4);
    unsigned bsw2 = ((2 ^ ((lane >> 1) & 3)) << 4);
    unsigned bsw3 = ((3 ^ ((lane >> 1) & 3)) << 4);

    char* outb = ((char*)g_xwp)
               + (size_t)(blockIdx.x * 128 + n0 + (lane >> 2)) * 1600
               + (lane & 3) * 16;

#pragma unroll 1
    for (int k = 0; k < 25; k++) {
        unsigned wk = wrow + k * 2048;
        float c0[4] = {0,0,0,0}, c1[4] = {0,0,0,0};
        float c2[4] = {0,0,0,0}, c3[4] = {0,0,0,0};
        unsigned b0, b1, b2, b3;
        ldsm4t(b0, b1, b2, b3, wk + bsw0);
        mma16816(c0, A0, b0, b1); mma16816(c0, A1, b2, b3);
        ldsm4t(b0, b1, b2, b3, wk + bsw1);
        mma16816(c1, A0, b0, b1); mma16816(c1, A1, b2, b3);
        ldsm4t(b0, b1, b2, b3, wk + bsw2);
        mma16816(c2, A0, b0, b1); mma16816(c2, A1, b2, b3);
        ldsm4t(b0, b1, b2, b3, wk + bsw3);
        mma16816(c3, A0, b0, b1); mma16816(c3, A1, b2, b3);

        uint4 v0, v1;
        v0.x = h2b(c0[0], c0[1]); v0.y = h2b(c1[0], c1[1]);
        v0.z = h2b(c2[0], c2[1]); v0.w = h2b(c3[0], c3[1]);
        v1.x = h2b(c0[2], c0[3]); v1.y = h2b(c1[2], c1[3]);
        v1.z = h2b(c2[2], c2[3]); v1.w = h2b(c3[2], c3[3]);
        *(uint4*)(outb + k * 64) = v0;                   // row r
        *(uint4*)(outb + k * 64 + 8 * 1600) = v1;        // row r+8
    }

    // k = 25: root transform (fp32 permuted) + rdot (attW loaded directly)
    {
        unsigned wk = wrow + 25 * 2048;
        float c0[4] = {0,0,0,0}, c1[4] = {0,0,0,0};
        float c2[4] = {0,0,0,0}, c3[4] = {0,0,0,0};
        unsigned b0, b1, b2, b3;
        ldsm4t(b0, b1, b2, b3, wk + bsw0);
        mma16816(c0, A0, b0, b1); mma16816(c0, A1, b2, b3);
        ldsm4t(b0, b1, b2, b3, wk + bsw1);
        mma16816(c1, A0, b0, b1); mma16816(c1, A1, b2, b3);
        ldsm4t(b0, b1, b2, b3, wk + bsw2);
        mma16816(c2, A0, b0, b1); mma16816(c2, A1, b2, b3);
        ldsm4t(b0, b1, b2, b3, wk + bsw3);
        mma16816(c3, A0, b0, b1); mma16816(c3, A1, b2, b3);

        int node = blockIdx.x * 128 + n0 + (lane >> 2);
        float* xo = g_xrb + (size_t)node * 32 + (lane & 3) * 8;
        *(float4*)(xo)       = make_float4(c0[0], c0[1], c1[0], c1[1]);
        *(float4*)(xo + 4)   = make_float4(c2[0], c2[1], c3[0], c3[1]);
        *(float4*)(xo + 256) = make_float4(c0[2], c0[3], c1[2], c1[3]);
        *(float4*)(xo + 260) = make_float4(c2[2], c2[3], c3[2], c3[3]);

        // att1p[8q+m] = attW[16*(m>=4) + 8*((m&3)>=2) + 2q + (m&1)]
        int q = lane & 3;
        float2 w0 = __ldg((const float2*)(attW + 2 * q));
        float2 w1 = __ldg((const float2*)(attW + 8 + 2 * q));
        float2 w2 = __ldg((const float2*)(attW + 16 + 2 * q));
        float2 w3 = __ldg((const float2*)(attW + 24 + 2 * q));
        float dr  = c0[0]*w0.x + c0[1]*w0.y + c1[0]*w1.x + c1[1]*w1.y
                  + c2[0]*w2.x + c2[1]*w2.y + c3[0]*w3.x + c3[1]*w3.y;
        float dr8 = c0[2]*w0.x + c0[3]*w0.y + c1[2]*w1.x + c1[3]*w1.y
                  + c2[2]*w2.x + c2[3]*w2.y + c3[2]*w3.x + c3[3]*w3.y;
        dr  += __shfl_xor_sync(0xffffffffu, dr, 1);
        dr  += __shfl_xor_sync(0xffffffffu, dr, 2);
        dr8 += __shfl_xor_sync(0xffffffffu, dr8, 1);
        dr8 += __shfl_xor_sync(0xffffffffu, dr8, 2);
        if ((lane & 3) == 0) {
            g_rdot[node]     = dr;
            g_rdot[node + 8] = dr8;
        }
    }
}

// ---------------------------------------------------------------------------
// K3: bucket-ordered edge pass, 8 lanes/edge, paired-row LDG.128 gather.
// ---------------------------------------------------------------------------
__global__ __launch_bounds__(256) void k3_edge()
{
    int t = blockIdx.x * 256 + threadIdx.x;
    int j   = t >> 3;
    int sub = t & 7;

    uint4 rc = __ldg(g_rec + j);
    int row = (int)rc.x, col = (int)rc.y;
    float p0 = __uint_as_float(rc.z) * 4.f;
    float p1 = __uint_as_float(rc.w) * 4.f;
    float fl0 = floorf(p0), fl1 = floorf(p1);
    float fr0 = p0 - fl0,   fr1 = p1 - fl1;
    int w0 = (int)fl0 + 5 * (int)fl1;

    const char* basep = (const char*)g_xwp + (size_t)col * 1600 + (sub << 4);
    uint4 qa = __ldg((const uint4*)(basep + w0 * 64));          // taps (0,0)/(1,0)
    uint4 qb = __ldg((const uint4*)(basep + (w0 + 5) * 64));    // taps (0,1)/(1,1)

    float fa = (sub & 4) ? fr0 : (1.f - fr0);
    unsigned ua = h2b(fa * (1.f - fr1), fa * (1.f - fr1));
    unsigned ub = h2b(fa * fr1,         fa * fr1);
    __half2 ha = *(__half2*)&ua, hb = *(__half2*)&ub;

    __half2 h0 = __hmul2(ha, *(__half2*)&qa.x);
    __half2 h1 = __hmul2(ha, *(__half2*)&qa.y);
    __half2 h2 = __hmul2(ha, *(__half2*)&qa.z);
    __half2 h3 = __hmul2(ha, *(__half2*)&qa.w);
    h0 = __hfma2(hb, *(__half2*)&qb.x, h0);
    h1 = __hfma2(hb, *(__half2*)&qb.y, h1);
    h2 = __hfma2(hb, *(__half2*)&qb.z, h2);
    h3 = __hfma2(hb, *(__half2*)&qb.w, h3);

    unsigned uu;
    uu = __shfl_xor_sync(0xffffffffu, *(unsigned*)&h0, 4);
    h0 = __hadd2(h0, *(__half2*)&uu);
    uu = __shfl_xor_sync(0xffffffffu, *(unsigned*)&h1, 4);
    h1 = __hadd2(h1, *(__half2*)&uu);
    uu = __shfl_xor_sync(0xffffffffu, *(unsigned*)&h2, 4);
    h2 = __hadd2(h2, *(__half2*)&uu);
    uu = __shfl_xor_sync(0xffffffffu, *(unsigned*)&h3, 4);
    h3 = __hadd2(h3, *(__half2*)&uu);

    float2 f0 = __half22float2(h0), f1 = __half22float2(h1);
    float2 f2 = __half22float2(h2), f3 = __half22float2(h3);

    int s = sub & 3;
    float4 A0 = __ldg(((const float4*)g_att2p) + 2 * s);
    float4 A1 = __ldg(((const float4*)g_att2p) + 2 * s + 1);
    float d = f0.x*A0.x + f0.y*A0.y + f1.x*A0.z + f1.y*A0.w
            + f2.x*A1.x + f2.y*A1.y + f3.x*A1.z + f3.y*A1.w;
    d += __shfl_xor_sync(0xffffffffu, d, 1);
    d += __shfl_xor_sync(0xffffffffu, d, 2);

    float alpha = d + __ldg(g_rdot + row);
    alpha = (alpha > 0.f) ? alpha : 0.2f * alpha;    // leaky relu
    float ex = __expf(alpha);       // softmax max-shift cancels in the ratio

    if (sub == 0) atomicAdd(g_denom + row, ex);

    float* ap = g_acc + (size_t)row * 32 + s * 8 + (sub & 4);
    float4 wv = (sub & 4)
        ? make_float4(f2.x * ex, f2.y * ex, f3.x * ex, f3.y * ex)
        : make_float4(f0.x * ex, f0.y * ex, f1.x * ex, f1.y * ex);
    asm volatile("red.global.add.v4.f32 [%0], {%1,%2,%3,%4};"
                 :: "l"(ap), "f"(wv.x), "f"(wv.y), "f"(wv.z), "f"(wv.w)
                 : "memory");
}

// ---------------------------------------------------------------------------
// K4: out = unpermute( acc/(denom+1e-16) + x_root_perm + bias_perm )
//     + restore g_bcnt=0 invariant for the next launch
// ---------------------------------------------------------------------------
__global__ __launch_bounds__(256) void k4_out(float* __restrict__ out)
{
    if (blockIdx.x == 0 && threadIdx.x < NBUK) g_bcnt[threadIdx.x] = 0;

    int i = blockIdx.x * 256 + threadIdx.x;     // 800000 = NN*8
    int n = i >> 3, g = i & 7;
    float r = 1.f / (g_denom[n] + 1e-16f);
    const float* ap  = g_acc + (size_t)n * 32;
    const float* xp_ = g_xrb + (size_t)n * 32;
    int h  = (g >> 2) & 1;
    int bb = (g >> 1) & 1;
    int pos0 = 8 * ((2 * g) & 3)     + 4 * h + 2 * bb;
    int pos1 = 8 * ((2 * g + 1) & 3) + 4 * h + 2 * bb;
    float2 u0 = *(const float2*)(ap + pos0);
    float2 u1 = *(const float2*)(ap + pos1);
    float2 x0 = *(const float2*)(xp_ + pos0);
    float2 x1 = *(const float2*)(xp_ + pos1);
    float2 b0 = *(const float2*)(g_biasp + pos0);
    float2 b1 = *(const float2*)(g_biasp + pos1);
    float4 o;
    o.x = fmaf(u0.x, r, x0.x + b0.x);
    o.y = fmaf(u0.y, r, x0.y + b0.y);
    o.z = fmaf(u1.x, r, x1.x + b1.x);
    o.w = fmaf(u1.y, r, x1.y + b1.y);
    ((float4*)out)[i] = o;
}

extern "C" void kernel_launch(void* const* d_in, const int* in_sizes, int n_in,
                              void* d_out, int out_size)
{
    const float* x      = (const float*)d_in[0];
    const int*   ei     = (const int*)d_in[1];
    const float* pseudo = (const float*)d_in[2];
    const float* W      = (const float*)d_in[3];
    const float* rootW  = (const float*)d_in[4];
    const float* attW   = (const float*)d_in[5];
    const float* bias   = (const float*)d_in[6];
    float* out = (float*)d_out;

    static cudaStream_t s_side = nullptr;
    static cudaEvent_t evF = nullptr, evJ = nullptr;
    if (!s_side) {
        cudaFuncSetAttribute(k2_mma,
            cudaFuncAttributeMaxDynamicSharedMemorySize, 61440);
        cudaStreamCreateWithFlags(&s_side, cudaStreamNonBlocking);
        cudaEventCreateWithFlags(&evF, cudaEventDisableTiming);
        cudaEventCreateWithFlags(&evJ, cudaEventDisableTiming);
    }

    // fork: sort chain + tables on side stream (depends only on ei/pseudo/attW/bias)
    cudaEventRecord(evF, 0);
    cudaStreamWaitEvent(s_side, evF, 0);
    s1_hist<<<625, 256, 0, s_side>>>(ei);
    s2_scan<<<1, 128, 0, s_side>>>(attW, bias);
    s3_scat<<<625, 256, 0, s_side>>>(ei, pseudo);
    cudaEventRecord(evJ, s_side);

    // main chain: node-side work (depends only on x/W/attW)
    k1_conv<<<(NN + 255) / 256, 256>>>(x);
    k2_mma <<<NNP / 128, 256, 61440>>>(W, rootW, attW);

    // join, then edge pass + epilogue
    cudaStreamWaitEvent(0, evJ, 0);
    k3_edge<<<(NE * 8) / 256, 256>>>();
    k4_out <<<3125, 256>>>(out);
}

// round 14
// speedup vs baseline: 1.2958x; 1.0644x over previous
#include <cuda_runtime.h>
#include <cuda_fp16.h>

#define NN 100000
#define NNP 100096          // padded to 128-node k2 blocks (782 * 128)
#define NE 1600000
#define NBUK 98             // col buckets of 1024 nodes

// fp16 copy of x
__device__ __half g_xh[(size_t)NNP * 32];
// xw' (PERMUTED feature layout) fp16: [NNP][25 kernels][64B]
__device__ uint2 g_xwp[(size_t)NNP * 200];
__device__ float g_att2p[32];                // attW[32..64) permuted
__device__ float g_biasp[32];                // bias permuted
__device__ float g_acc[(size_t)NN * 32];     // permuted space
__device__ float g_xrb[(size_t)NNP * 32];    // x_root, PERMUTED fp32 (from k2)
__device__ float g_rdot[NNP];
__device__ float g_denom[NN];
// edge bucketing (g_bcnt is zero at entry; k4 restores the invariant)
__device__ int   g_bcnt[NBUK];
__device__ int   g_bcur[NBUK];
__device__ uint4 g_rec[NE];                  // {row, col, pseudo.x, pseudo.y}

__device__ __forceinline__ unsigned h2b(float a, float b) {
    unsigned r; asm("cvt.rn.f16x2.f32 %0,%2,%1;" : "=r"(r) : "f"(a), "f"(b));
    return r;   // low half = a
}
__device__ __forceinline__ unsigned sm_u32(const void* p) {
    unsigned r;
    asm("{.reg .u64 t; cvta.to.shared.u64 t, %1; cvt.u32.u64 %0, t;}"
        : "=r"(r) : "l"(p));
    return r;
}
__device__ __forceinline__ void ldsm4(unsigned& r0, unsigned& r1,
                                      unsigned& r2, unsigned& r3, unsigned a) {
    asm volatile("ldmatrix.sync.aligned.m8n8.x4.shared.b16 {%0,%1,%2,%3}, [%4];"
                 : "=r"(r0), "=r"(r1), "=r"(r2), "=r"(r3) : "r"(a));
}
__device__ __forceinline__ void ldsm4t(unsigned& r0, unsigned& r1,
                                       unsigned& r2, unsigned& r3, unsigned a) {
    asm volatile("ldmatrix.sync.aligned.m8n8.x4.trans.shared.b16 {%0,%1,%2,%3}, [%4];"
                 : "=r"(r0), "=r"(r1), "=r"(r2), "=r"(r3) : "r"(a));
}
__device__ __forceinline__ void mma16816(float* c, const unsigned* a,
                                         unsigned b0, unsigned b1) {
    asm volatile("mma.sync.aligned.m16n8k16.row.col.f32.f16.f16.f32 "
                 "{%0,%1,%2,%3}, {%4,%5,%6,%7}, {%8,%9}, {%0,%1,%2,%3};"
                 : "+f"(c[0]), "+f"(c[1]), "+f"(c[2]), "+f"(c[3])
                 : "r"(a[0]), "r"(a[1]), "r"(a[2]), "r"(a[3]), "r"(b0), "r"(b1));
}

// ---------------------------------------------------------------------------
// S1: per-bucket histogram of col (smem-staged). g_bcnt is 0 at entry.
// ---------------------------------------------------------------------------
__global__ __launch_bounds__(256) void s1_hist(const int* __restrict__ ei)
{
    __shared__ int h[NBUK];
    int tid = threadIdx.x;
    if (tid < NBUK) h[tid] = 0;
    __syncthreads();
    int base = blockIdx.x * 2560;          // 625 blocks * 2560 = NE
#pragma unroll
    for (int i = 0; i < 10; i++) {
        int col = __ldg(ei + NE + base + i * 256 + tid);
        atomicAdd(&h[col >> 10], 1);
    }
    __syncthreads();
    if (tid < NBUK) atomicAdd(&g_bcnt[tid], h[tid]);
}

// ---------------------------------------------------------------------------
// S2: exclusive scan of bucket counts + permuted att2/bias tables
//     (tables consumed only by k3/k4, which are ordered after this via evJ)
// ---------------------------------------------------------------------------
__global__ void s2_scan(const float* __restrict__ attW,
                        const float* __restrict__ bias)
{
    int i = threadIdx.x;                 // 128 threads
    if (i == 0) {
        int s = 0;
        for (int b = 0; b < NBUK; b++) { int c = g_bcnt[b]; g_bcur[b] = s; s += c; }
    }
    if (i < 32) {
        int sub = i >> 2, j = i & 3;
        int c = sub >> 1, h = sub & 1;
        int f = 16 * h + 8 * (j >> 1) + 2 * c + (j & 1);
        g_att2p[i] = attW[32 + f];
        g_biasp[i] = bias[f];
    }
}

// ---------------------------------------------------------------------------
// S3: scatter edges into bucket-ordered record array (block-staged)
// ---------------------------------------------------------------------------
__global__ __launch_bounds__(256) void s3_scat(
    const int* __restrict__ ei, const float* __restrict__ pseudo)
{
    __shared__ int h[NBUK], st[NBUK];
    int tid = threadIdx.x;
    if (tid < NBUK) h[tid] = 0;
    __syncthreads();
    int base = blockIdx.x * 2560;
    int myrow[10], mycol[10];
    float2 myps[10];
#pragma unroll
    for (int i = 0; i < 10; i++) {
        int e = base + i * 256 + tid;
        myrow[i] = __ldg(ei + e);
        mycol[i] = __ldg(ei + NE + e);
        myps[i]  = __ldg((const float2*)pseudo + e);
        atomicAdd(&h[mycol[i] >> 10], 1);
    }
    __syncthreads();
    if (tid < NBUK) st[tid] = atomicAdd(&g_bcur[tid], h[tid]);
    __syncthreads();
    if (tid < NBUK) h[tid] = 0;
    __syncthreads();
#pragma unroll
    for (int i = 0; i < 10; i++) {
        int b = mycol[i] >> 10;
        int pos = st[b] + atomicAdd(&h[b], 1);
        g_rec[pos] = make_uint4((unsigned)myrow[i], (unsigned)mycol[i],
                                __float_as_uint(myps[i].x),
                                __float_as_uint(myps[i].y));
    }
}

// ---------------------------------------------------------------------------
// K1 (fine-grained): thread i zeroes one float4 of acc; i<400k converts one
// 16B chunk of x->fp16; i<100k zeroes denom. 3125 blocks — full occupancy.
// ---------------------------------------------------------------------------
__global__ __launch_bounds__(256) void k1_conv(const float* __restrict__ x)
{
    int i = blockIdx.x * 256 + threadIdx.x;     // 800000 threads
    ((float4*)g_acc)[i] = make_float4(0.f, 0.f, 0.f, 0.f);
    if (i < 400000) {                           // NN*32/8 uint4 chunks of xh
        const float4* xp = ((const float4*)x) + i * 2;
        float4 t0 = xp[0], t1 = xp[1];
        uint4 h;
        h.x = h2b(t0.x, t0.y); h.y = h2b(t0.z, t0.w);
        h.z = h2b(t1.x, t1.y); h.w = h2b(t1.z, t1.w);
        ((uint4*)g_xh)[i] = h;
    }
    if (i < NN) g_denom[i] = 0.f;
}

// ---------------------------------------------------------------------------
// K2: raw mma.m16n8k16, 26 kernels (25 spline + root).
//   rdot epilogue reads attW directly (permutation folded into addressing).
// ---------------------------------------------------------------------------
__global__ __launch_bounds__(256) void k2_mma(
    const float* __restrict__ W, const float* __restrict__ rootW,
    const float* __restrict__ attW)
{
    extern __shared__ __align__(16) char smraw[];
    uint4* Wd = (uint4*)smraw;                 // 3328 uint4 (26 * 2048B)
    uint4* Ad = (uint4*)(smraw + 53248);       // 512 uint4

    int tid = threadIdx.x;
    {
#pragma unroll
        for (int i = 0; i < 13; i++) {
            int ch = tid + 256 * i;            // 3328 exact
            int kk = ch >> 7, r = (ch >> 2) & 31, c = ch & 3;
            const float* src = (kk < 25 ? W + kk * 1024 : rootW) + r * 32 + c * 8;
            float4 s0 = __ldg((const float4*)src);
            float4 s1 = __ldg((const float4*)src + 1);
            uint4 v;
            v.x = h2b(s0.x, s0.y); v.y = h2b(s0.z, s0.w);
            v.z = h2b(s1.x, s1.y); v.w = h2b(s1.z, s1.w);
            Wd[kk * 128 + r * 4 + (c ^ ((r >> 1) & 3))] = v;
        }
        int n0g = blockIdx.x * 128;
        const uint4* xsrc = ((const uint4*)g_xh) + (size_t)n0g * 4;
#pragma unroll
        for (int i = 0; i < 2; i++) {
            int ch = tid + 256 * i;
            int nd = ch >> 2, c = ch & 3;
            Ad[nd * 4 + (c ^ ((nd >> 1) & 3))] = xsrc[ch];
        }
    }
    __syncthreads();

    int lane = tid & 31, warp = tid >> 5;
    int n0 = warp * 16;
    unsigned Ab = sm_u32(Ad), Wb = sm_u32(Wd);

    int Lr = lane & 7, mg = lane >> 3;
    int anode = n0 + Lr + 8 * (mg & 1);
    int acb = mg >> 1;
    unsigned A0[4], A1[4];
    ldsm4(A0[0], A0[1], A0[2], A0[3],
          Ab + anode * 64 + (((acb)     ^ ((anode >> 1) & 3)) << 4));
    ldsm4(A1[0], A1[1], A1[2], A1[3],
          Ab + anode * 64 + (((acb + 2) ^ ((anode >> 1) & 3)) << 4));

    unsigned wrow = Wb + lane * 64;
    unsigned bsw0 = ((0 ^ ((lane >> 1) & 3)) << 4);
    unsigned bsw1 = ((1 ^ ((lane >> 1) & 3)) << 4);
    unsigned bsw2 = ((2 ^ ((lane >> 1) & 3)) << 4);
    unsigned bsw3 = ((3 ^ ((lane >> 1) & 3)) << 4);

    char* outb = ((char*)g_xwp)
               + (size_t)(blockIdx.x * 128 + n0 + (lane >> 2)) * 1600
               + (lane & 3) * 16;

#pragma unroll 1
    for (int k = 0; k < 25; k++) {
        unsigned wk = wrow + k * 2048;
        float c0[4] = {0,0,0,0}, c1[4] = {0,0,0,0};
        float c2[4] = {0,0,0,0}, c3[4] = {0,0,0,0};
        unsigned b0, b1, b2, b3;
        ldsm4t(b0, b1, b2, b3, wk + bsw0);
        mma16816(c0, A0, b0, b1); mma16816(c0, A1, b2, b3);
        ldsm4t(b0, b1, b2, b3, wk + bsw1);
        mma16816(c1, A0, b0, b1); mma16816(c1, A1, b2, b3);
        ldsm4t(b0, b1, b2, b3, wk + bsw2);
        mma16816(c2, A0, b0, b1); mma16816(c2, A1, b2, b3);
        ldsm4t(b0, b1, b2, b3, wk + bsw3);
        mma16816(c3, A0, b0, b1); mma16816(c3, A1, b2, b3);

        uint4 v0, v1;
        v0.x = h2b(c0[0], c0[1]); v0.y = h2b(c1[0], c1[1]);
        v0.z = h2b(c2[0], c2[1]); v0.w = h2b(c3[0], c3[1]);
        v1.x = h2b(c0[2], c0[3]); v1.y = h2b(c1[2], c1[3]);
        v1.z = h2b(c2[2], c2[3]); v1.w = h2b(c3[2], c3[3]);
        *(uint4*)(outb + k * 64) = v0;                   // row r
        *(uint4*)(outb + k * 64 + 8 * 1600) = v1;        // row r+8
    }

    // k = 25: root transform (fp32 permuted) + rdot (attW loaded directly)
    {
        unsigned wk = wrow + 25 * 2048;
        float c0[4] = {0,0,0,0}, c1[4] = {0,0,0,0};
        float c2[4] = {0,0,0,0}, c3[4] = {0,0,0,0};
        unsigned b0, b1, b2, b3;
        ldsm4t(b0, b1, b2, b3, wk + bsw0);
        mma16816(c0, A0, b0, b1); mma16816(c0, A1, b2, b3);
        ldsm4t(b0, b1, b2, b3, wk + bsw1);
        mma16816(c1, A0, b0, b1); mma16816(c1, A1, b2, b3);
        ldsm4t(b0, b1, b2, b3, wk + bsw2);
        mma16816(c2, A0, b0, b1); mma16816(c2, A1, b2, b3);
        ldsm4t(b0, b1, b2, b3, wk + bsw3);
        mma16816(c3, A0, b0, b1); mma16816(c3, A1, b2, b3);

        int node = blockIdx.x * 128 + n0 + (lane >> 2);
        float* xo = g_xrb + (size_t)node * 32 + (lane & 3) * 8;
        *(float4*)(xo)       = make_float4(c0[0], c0[1], c1[0], c1[1]);
        *(float4*)(xo + 4)   = make_float4(c2[0], c2[1], c3[0], c3[1]);
        *(float4*)(xo + 256) = make_float4(c0[2], c0[3], c1[2], c1[3]);
        *(float4*)(xo + 260) = make_float4(c2[2], c2[3], c3[2], c3[3]);

        // att1p[8q+m] = attW[16*(m>=4) + 8*((m&3)>=2) + 2q + (m&1)]
        int q = lane & 3;
        float2 w0 = __ldg((const float2*)(attW + 2 * q));
        float2 w1 = __ldg((const float2*)(attW + 8 + 2 * q));
        float2 w2 = __ldg((const float2*)(attW + 16 + 2 * q));
        float2 w3 = __ldg((const float2*)(attW + 24 + 2 * q));
        float dr  = c0[0]*w0.x + c0[1]*w0.y + c1[0]*w1.x + c1[1]*w1.y
                  + c2[0]*w2.x + c2[1]*w2.y + c3[0]*w3.x + c3[1]*w3.y;
        float dr8 = c0[2]*w0.x + c0[3]*w0.y + c1[2]*w1.x + c1[3]*w1.y
                  + c2[2]*w2.x + c2[3]*w2.y + c3[2]*w3.x + c3[3]*w3.y;
        dr  += __shfl_xor_sync(0xffffffffu, dr, 1);
        dr  += __shfl_xor_sync(0xffffffffu, dr, 2);
        dr8 += __shfl_xor_sync(0xffffffffu, dr8, 1);
        dr8 += __shfl_xor_sync(0xffffffffu, dr8, 2);
        if ((lane & 3) == 0) {
            g_rdot[node]     = dr;
            g_rdot[node + 8] = dr8;
        }
    }
}

// ---------------------------------------------------------------------------
// K3: bucket-ordered edge pass, 8 lanes/edge, paired-row LDG.128 gather.
// ---------------------------------------------------------------------------
__global__ __launch_bounds__(256) void k3_edge()
{
    int t = blockIdx.x * 256 + threadIdx.x;
    int j   = t >> 3;
    int sub = t & 7;

    uint4 rc = __ldg(g_rec + j);
    int row = (int)rc.x, col = (int)rc.y;
    float p0 = __uint_as_float(rc.z) * 4.f;
    float p1 = __uint_as_float(rc.w) * 4.f;
    float fl0 = floorf(p0), fl1 = floorf(p1);
    float fr0 = p0 - fl0,   fr1 = p1 - fl1;
    int w0 = (int)fl0 + 5 * (int)fl1;

    const char* basep = (const char*)g_xwp + (size_t)col * 1600 + (sub << 4);
    uint4 qa = __ldg((const uint4*)(basep + w0 * 64));          // taps (0,0)/(1,0)
    uint4 qb = __ldg((const uint4*)(basep + (w0 + 5) * 64));    // taps (0,1)/(1,1)

    float fa = (sub & 4) ? fr0 : (1.f - fr0);
    unsigned ua = h2b(fa * (1.f - fr1), fa * (1.f - fr1));
    unsigned ub = h2b(fa * fr1,         fa * fr1);
    __half2 ha = *(__half2*)&ua, hb = *(__half2*)&ub;

    __half2 h0 = __hmul2(ha, *(__half2*)&qa.x);
    __half2 h1 = __hmul2(ha, *(__half2*)&qa.y);
    __half2 h2 = __hmul2(ha, *(__half2*)&qa.z);
    __half2 h3 = __hmul2(ha, *(__half2*)&qa.w);
    h0 = __hfma2(hb, *(__half2*)&qb.x, h0);
    h1 = __hfma2(hb, *(__half2*)&qb.y, h1);
    h2 = __hfma2(hb, *(__half2*)&qb.z, h2);
    h3 = __hfma2(hb, *(__half2*)&qb.w, h3);

    unsigned uu;
    uu = __shfl_xor_sync(0xffffffffu, *(unsigned*)&h0, 4);
    h0 = __hadd2(h0, *(__half2*)&uu);
    uu = __shfl_xor_sync(0xffffffffu, *(unsigned*)&h1, 4);
    h1 = __hadd2(h1, *(__half2*)&uu);
    uu = __shfl_xor_sync(0xffffffffu, *(unsigned*)&h2, 4);
    h2 = __hadd2(h2, *(__half2*)&uu);
    uu = __shfl_xor_sync(0xffffffffu, *(unsigned*)&h3, 4);
    h3 = __hadd2(h3, *(__half2*)&uu);

    float2 f0 = __half22float2(h0), f1 = __half22float2(h1);
    float2 f2 = __half22float2(h2), f3 = __half22float2(h3);

    int s = sub & 3;
    float4 A0 = __ldg(((const float4*)g_att2p) + 2 * s);
    float4 A1 = __ldg(((const float4*)g_att2p) + 2 * s + 1);
    float d = f0.x*A0.x + f0.y*A0.y + f1.x*A0.z + f1.y*A0.w
            + f2.x*A1.x + f2.y*A1.y + f3.x*A1.z + f3.y*A1.w;
    d += __shfl_xor_sync(0xffffffffu, d, 1);
    d += __shfl_xor_sync(0xffffffffu, d, 2);

    float alpha = d + __ldg(g_rdot + row);
    alpha = (alpha > 0.f) ? alpha : 0.2f * alpha;    // leaky relu
    float ex = __expf(alpha);       // softmax max-shift cancels in the ratio

    if (sub == 0) atomicAdd(g_denom + row, ex);

    float* ap = g_acc + (size_t)row * 32 + s * 8 + (sub & 4);
    float4 wv = (sub & 4)
        ? make_float4(f2.x * ex, f2.y * ex, f3.x * ex, f3.y * ex)
        : make_float4(f0.x * ex, f0.y * ex, f1.x * ex, f1.y * ex);
    asm volatile("red.global.add.v4.f32 [%0], {%1,%2,%3,%4};"
                 :: "l"(ap), "f"(wv.x), "f"(wv.y), "f"(wv.z), "f"(wv.w)
                 : "memory");
}

// ---------------------------------------------------------------------------
// K4: out = unpermute( acc/(denom+1e-16) + x_root_perm + bias_perm )
//     + restore g_bcnt=0 invariant for the next launch
// ---------------------------------------------------------------------------
__global__ __launch_bounds__(256) void k4_out(float* __restrict__ out)
{
    if (blockIdx.x == 0 && threadIdx.x < NBUK) g_bcnt[threadIdx.x] = 0;

    int i = blockIdx.x * 256 + threadIdx.x;     // 800000 = NN*8
    int n = i >> 3, g = i & 7;
    float r = 1.f / (g_denom[n] + 1e-16f);
    const float* ap  = g_acc + (size_t)n * 32;
    const float* xp_ = g_xrb + (size_t)n * 32;
    int h  = (g >> 2) & 1;
    int bb = (g >> 1) & 1;
    int pos0 = 8 * ((2 * g) & 3)     + 4 * h + 2 * bb;
    int pos1 = 8 * ((2 * g + 1) & 3) + 4 * h + 2 * bb;
    float2 u0 = *(const float2*)(ap + pos0);
    float2 u1 = *(const float2*)(ap + pos1);
    float2 x0 = *(const float2*)(xp_ + pos0);
    float2 x1 = *(const float2*)(xp_ + pos1);
    float2 b0 = *(const float2*)(g_biasp + pos0);
    float2 b1 = *(const float2*)(g_biasp + pos1);
    float4 o;
    o.x = fmaf(u0.x, r, x0.x + b0.x);
    o.y = fmaf(u0.y, r, x0.y + b0.y);
    o.z = fmaf(u1.x, r, x1.x + b1.x);
    o.w = fmaf(u1.y, r, x1.y + b1.y);
    ((float4*)out)[i] = o;
}

extern "C" void kernel_launch(void* const* d_in, const int* in_sizes, int n_in,
                              void* d_out, int out_size)
{
    const float* x      = (const float*)d_in[0];
    const int*   ei     = (const int*)d_in[1];
    const float* pseudo = (const float*)d_in[2];
    const float* W      = (const float*)d_in[3];
    const float* rootW  = (const float*)d_in[4];
    const float* attW   = (const float*)d_in[5];
    const float* bias   = (const float*)d_in[6];
    float* out = (float*)d_out;

    static cudaStream_t s_side = nullptr;
    static cudaEvent_t evF = nullptr, evJ = nullptr;
    if (!s_side) {
        cudaFuncSetAttribute(k2_mma,
            cudaFuncAttributeMaxDynamicSharedMemorySize, 61440);
        cudaStreamCreateWithFlags(&s_side, cudaStreamNonBlocking);
        cudaEventCreateWithFlags(&evF, cudaEventDisableTiming);
        cudaEventCreateWithFlags(&evJ, cudaEventDisableTiming);
    }

    // fork: sort chain + tables on side stream (depends only on ei/pseudo/attW/bias)
    cudaEventRecord(evF, 0);
    cudaStreamWaitEvent(s_side, evF, 0);
    s1_hist<<<625, 256, 0, s_side>>>(ei);
    s2_scan<<<1, 128, 0, s_side>>>(attW, bias);
    s3_scat<<<625, 256, 0, s_side>>>(ei, pseudo);
    cudaEventRecord(evJ, s_side);

    // main chain: node-side work (depends only on x/W/attW)
    k1_conv<<<3125, 256>>>(x);
    k2_mma <<<NNP / 128, 256, 61440>>>(W, rootW, attW);

    // join, then edge pass + epilogue
    cudaStreamWaitEvent(0, evJ, 0);
    k3_edge<<<(NE * 8) / 256, 256>>>();
    k4_out <<<3125, 256>>>(out);
}

// round 15
// speedup vs baseline: 1.3159x; 1.0156x over previous
#include <cuda_runtime.h>
#include <cuda_fp16.h>

#define NN 100000
#define NNP 100096          // padded to 128-node k2 blocks (782 * 128)
#define NE 1600000
#define NBUK 98             // col buckets of 1024 nodes

// fp16 copy of x
__device__ __half g_xh[(size_t)NNP * 32];
// xw' (PERMUTED feature layout) fp16: [NNP][25 kernels][64B]
__device__ uint2 g_xwp[(size_t)NNP * 200];
__device__ float g_att2p[32];                // attW[32..64) permuted
__device__ float g_biasp[32];                // bias permuted
__device__ float g_acc[(size_t)NN * 32];     // permuted space
__device__ float g_xrb[(size_t)NNP * 32];    // x_root, PERMUTED fp32 (from k2)
__device__ float g_rdot[NNP];
__device__ float g_denom[NN];
// edge bucketing (g_bcnt is zero at entry; k4 restores the invariant)
__device__ int   g_bcnt[NBUK];
__device__ int   g_bcur[NBUK];
__device__ uint4 g_rec[NE];                  // {row, col, pseudo.x, pseudo.y}

__device__ __forceinline__ unsigned h2b(float a, float b) {
    unsigned r; asm("cvt.rn.f16x2.f32 %0,%2,%1;" : "=r"(r) : "f"(a), "f"(b));
    return r;   // low half = a
}
__device__ __forceinline__ unsigned sm_u32(const void* p) {
    unsigned r;
    asm("{.reg .u64 t; cvta.to.shared.u64 t, %1; cvt.u32.u64 %0, t;}"
        : "=r"(r) : "l"(p));
    return r;
}
__device__ __forceinline__ void ldsm4(unsigned& r0, unsigned& r1,
                                      unsigned& r2, unsigned& r3, unsigned a) {
    asm volatile("ldmatrix.sync.aligned.m8n8.x4.shared.b16 {%0,%1,%2,%3}, [%4];"
                 : "=r"(r0), "=r"(r1), "=r"(r2), "=r"(r3) : "r"(a));
}
__device__ __forceinline__ void ldsm4t(unsigned& r0, unsigned& r1,
                                       unsigned& r2, unsigned& r3, unsigned a) {
    asm volatile("ldmatrix.sync.aligned.m8n8.x4.trans.shared.b16 {%0,%1,%2,%3}, [%4];"
                 : "=r"(r0), "=r"(r1), "=r"(r2), "=r"(r3) : "r"(a));
}
__device__ __forceinline__ void mma16816(float* c, const unsigned* a,
                                         unsigned b0, unsigned b1) {
    asm volatile("mma.sync.aligned.m16n8k16.row.col.f32.f16.f16.f32 "
                 "{%0,%1,%2,%3}, {%4,%5,%6,%7}, {%8,%9}, {%0,%1,%2,%3};"
                 : "+f"(c[0]), "+f"(c[1]), "+f"(c[2]), "+f"(c[3])
                 : "r"(a[0]), "r"(a[1]), "r"(a[2]), "r"(a[3]), "r"(b0), "r"(b1));
}

// ---------------------------------------------------------------------------
// S1: per-bucket histogram of col (smem-staged). g_bcnt is 0 at entry.
// ---------------------------------------------------------------------------
__global__ __launch_bounds__(256) void s1_hist(const int* __restrict__ ei)
{
    __shared__ int h[NBUK];
    int tid = threadIdx.x;
    if (tid < NBUK) h[tid] = 0;
    __syncthreads();
    int base = blockIdx.x * 2560;          // 625 blocks * 2560 = NE
#pragma unroll
    for (int i = 0; i < 10; i++) {
        int col = __ldg(ei + NE + base + i * 256 + tid);
        atomicAdd(&h[col >> 10], 1);
    }
    __syncthreads();
    if (tid < NBUK) atomicAdd(&g_bcnt[tid], h[tid]);
}

// ---------------------------------------------------------------------------
// S2: exclusive scan of bucket counts + permuted att2/bias tables
// ---------------------------------------------------------------------------
__global__ void s2_scan(const float* __restrict__ attW,
                        const float* __restrict__ bias)
{
    int i = threadIdx.x;                 // 128 threads
    if (i == 0) {
        int s = 0;
        for (int b = 0; b < NBUK; b++) { int c = g_bcnt[b]; g_bcur[b] = s; s += c; }
    }
    if (i < 32) {
        int sub = i >> 2, j = i & 3;
        int c = sub >> 1, h = sub & 1;
        int f = 16 * h + 8 * (j >> 1) + 2 * c + (j & 1);
        g_att2p[i] = attW[32 + f];
        g_biasp[i] = bias[f];
    }
}

// ---------------------------------------------------------------------------
// S3: scatter edges into bucket-ordered record array (block-staged)
// ---------------------------------------------------------------------------
__global__ __launch_bounds__(256) void s3_scat(
    const int* __restrict__ ei, const float* __restrict__ pseudo)
{
    __shared__ int h[NBUK], st[NBUK];
    int tid = threadIdx.x;
    if (tid < NBUK) h[tid] = 0;
    __syncthreads();
    int base = blockIdx.x * 2560;
    int myrow[10], mycol[10];
    float2 myps[10];
#pragma unroll
    for (int i = 0; i < 10; i++) {
        int e = base + i * 256 + tid;
        myrow[i] = __ldg(ei + e);
        mycol[i] = __ldg(ei + NE + e);
        myps[i]  = __ldg((const float2*)pseudo + e);
        atomicAdd(&h[mycol[i] >> 10], 1);
    }
    __syncthreads();
    if (tid < NBUK) st[tid] = atomicAdd(&g_bcur[tid], h[tid]);
    __syncthreads();
    if (tid < NBUK) h[tid] = 0;
    __syncthreads();
#pragma unroll
    for (int i = 0; i < 10; i++) {
        int b = mycol[i] >> 10;
        int pos = st[b] + atomicAdd(&h[b], 1);
        g_rec[pos] = make_uint4((unsigned)myrow[i], (unsigned)mycol[i],
                                __float_as_uint(myps[i].x),
                                __float_as_uint(myps[i].y));
    }
}

// ---------------------------------------------------------------------------
// K1 (fine-grained): thread i zeroes one float4 of acc; i<400k converts one
// 16B chunk of x->fp16; i<100k zeroes denom. 3125 blocks — full occupancy.
// ---------------------------------------------------------------------------
__global__ __launch_bounds__(256) void k1_conv(const float* __restrict__ x)
{
    int i = blockIdx.x * 256 + threadIdx.x;     // 800000 threads
    ((float4*)g_acc)[i] = make_float4(0.f, 0.f, 0.f, 0.f);
    if (i < 400000) {                           // NN*32/8 uint4 chunks of xh
        const float4* xp = ((const float4*)x) + i * 2;
        float4 t0 = xp[0], t1 = xp[1];
        uint4 h;
        h.x = h2b(t0.x, t0.y); h.y = h2b(t0.z, t0.w);
        h.z = h2b(t1.x, t1.y); h.w = h2b(t1.z, t1.w);
        ((uint4*)g_xh)[i] = h;
    }
    if (i < NN) g_denom[i] = 0.f;
}

// ---------------------------------------------------------------------------
// K2: raw mma.m16n8k16, 26 kernels (25 spline + root).
// ---------------------------------------------------------------------------
__global__ __launch_bounds__(256) void k2_mma(
    const float* __restrict__ W, const float* __restrict__ rootW,
    const float* __restrict__ attW)
{
    extern __shared__ __align__(16) char smraw[];
    uint4* Wd = (uint4*)smraw;                 // 3328 uint4 (26 * 2048B)
    uint4* Ad = (uint4*)(smraw + 53248);       // 512 uint4

    int tid = threadIdx.x;
    {
#pragma unroll
        for (int i = 0; i < 13; i++) {
            int ch = tid + 256 * i;            // 3328 exact
            int kk = ch >> 7, r = (ch >> 2) & 31, c = ch & 3;
            const float* src = (kk < 25 ? W + kk * 1024 : rootW) + r * 32 + c * 8;
            float4 s0 = __ldg((const float4*)src);
            float4 s1 = __ldg((const float4*)src + 1);
            uint4 v;
            v.x = h2b(s0.x, s0.y); v.y = h2b(s0.z, s0.w);
            v.z = h2b(s1.x, s1.y); v.w = h2b(s1.z, s1.w);
            Wd[kk * 128 + r * 4 + (c ^ ((r >> 1) & 3))] = v;
        }
        int n0g = blockIdx.x * 128;
        const uint4* xsrc = ((const uint4*)g_xh) + (size_t)n0g * 4;
#pragma unroll
        for (int i = 0; i < 2; i++) {
            int ch = tid + 256 * i;
            int nd = ch >> 2, c = ch & 3;
            Ad[nd * 4 + (c ^ ((nd >> 1) & 3))] = xsrc[ch];
        }
    }
    __syncthreads();

    int lane = tid & 31, warp = tid >> 5;
    int n0 = warp * 16;
    unsigned Ab = sm_u32(Ad), Wb = sm_u32(Wd);

    int Lr = lane & 7, mg = lane >> 3;
    int anode = n0 + Lr + 8 * (mg & 1);
    int acb = mg >> 1;
    unsigned A0[4], A1[4];
    ldsm4(A0[0], A0[1], A0[2], A0[3],
          Ab + anode * 64 + (((acb)     ^ ((anode >> 1) & 3)) << 4));
    ldsm4(A1[0], A1[1], A1[2], A1[3],
          Ab + anode * 64 + (((acb + 2) ^ ((anode >> 1) & 3)) << 4));

    unsigned wrow = Wb + lane * 64;
    unsigned bsw0 = ((0 ^ ((lane >> 1) & 3)) << 4);
    unsigned bsw1 = ((1 ^ ((lane >> 1) & 3)) << 4);
    unsigned bsw2 = ((2 ^ ((lane >> 1) & 3)) << 4);
    unsigned bsw3 = ((3 ^ ((lane >> 1) & 3)) << 4);

    char* outb = ((char*)g_xwp)
               + (size_t)(blockIdx.x * 128 + n0 + (lane >> 2)) * 1600
               + (lane & 3) * 16;

#pragma unroll 1
    for (int k = 0; k < 25; k++) {
        unsigned wk = wrow + k * 2048;
        float c0[4] = {0,0,0,0}, c1[4] = {0,0,0,0};
        float c2[4] = {0,0,0,0}, c3[4] = {0,0,0,0};
        unsigned b0, b1, b2, b3;
        ldsm4t(b0, b1, b2, b3, wk + bsw0);
        mma16816(c0, A0, b0, b1); mma16816(c0, A1, b2, b3);
        ldsm4t(b0, b1, b2, b3, wk + bsw1);
        mma16816(c1, A0, b0, b1); mma16816(c1, A1, b2, b3);
        ldsm4t(b0, b1, b2, b3, wk + bsw2);
        mma16816(c2, A0, b0, b1); mma16816(c2, A1, b2, b3);
        ldsm4t(b0, b1, b2, b3, wk + bsw3);
        mma16816(c3, A0, b0, b1); mma16816(c3, A1, b2, b3);

        uint4 v0, v1;
        v0.x = h2b(c0[0], c0[1]); v0.y = h2b(c1[0], c1[1]);
        v0.z = h2b(c2[0], c2[1]); v0.w = h2b(c3[0], c3[1]);
        v1.x = h2b(c0[2], c0[3]); v1.y = h2b(c1[2], c1[3]);
        v1.z = h2b(c2[2], c2[3]); v1.w = h2b(c3[2], c3[3]);
        *(uint4*)(outb + k * 64) = v0;                   // row r
        *(uint4*)(outb + k * 64 + 8 * 1600) = v1;        // row r+8
    }

    // k = 25: root transform (fp32 permuted) + rdot (attW loaded directly)
    {
        unsigned wk = wrow + 25 * 2048;
        float c0[4] = {0,0,0,0}, c1[4] = {0,0,0,0};
        float c2[4] = {0,0,0,0}, c3[4] = {0,0,0,0};
        unsigned b0, b1, b2, b3;
        ldsm4t(b0, b1, b2, b3, wk + bsw0);
        mma16816(c0, A0, b0, b1); mma16816(c0, A1, b2, b3);
        ldsm4t(b0, b1, b2, b3, wk + bsw1);
        mma16816(c1, A0, b0, b1); mma16816(c1, A1, b2, b3);
        ldsm4t(b0, b1, b2, b3, wk + bsw2);
        mma16816(c2, A0, b0, b1); mma16816(c2, A1, b2, b3);
        ldsm4t(b0, b1, b2, b3, wk + bsw3);
        mma16816(c3, A0, b0, b1); mma16816(c3, A1, b2, b3);

        int node = blockIdx.x * 128 + n0 + (lane >> 2);
        float* xo = g_xrb + (size_t)node * 32 + (lane & 3) * 8;
        *(float4*)(xo)       = make_float4(c0[0], c0[1], c1[0], c1[1]);
        *(float4*)(xo + 4)   = make_float4(c2[0], c2[1], c3[0], c3[1]);
        *(float4*)(xo + 256) = make_float4(c0[2], c0[3], c1[2], c1[3]);
        *(float4*)(xo + 260) = make_float4(c2[2], c2[3], c3[2], c3[3]);

        // att1p[8q+m] = attW[16*(m>=4) + 8*((m&3)>=2) + 2q + (m&1)]
        int q = lane & 3;
        float2 w0 = __ldg((const float2*)(attW + 2 * q));
        float2 w1 = __ldg((const float2*)(attW + 8 + 2 * q));
        float2 w2 = __ldg((const float2*)(attW + 16 + 2 * q));
        float2 w3 = __ldg((const float2*)(attW + 24 + 2 * q));
        float dr  = c0[0]*w0.x + c0[1]*w0.y + c1[0]*w1.x + c1[1]*w1.y
                  + c2[0]*w2.x + c2[1]*w2.y + c3[0]*w3.x + c3[1]*w3.y;
        float dr8 = c0[2]*w0.x + c0[3]*w0.y + c1[2]*w1.x + c1[3]*w1.y
                  + c2[2]*w2.x + c2[3]*w2.y + c3[2]*w3.x + c3[3]*w3.y;
        dr  += __shfl_xor_sync(0xffffffffu, dr, 1);
        dr  += __shfl_xor_sync(0xffffffffu, dr, 2);
        dr8 += __shfl_xor_sync(0xffffffffu, dr8, 1);
        dr8 += __shfl_xor_sync(0xffffffffu, dr8, 2);
        if ((lane & 3) == 0) {
            g_rdot[node]     = dr;
            g_rdot[node + 8] = dr8;
        }
    }
}

// ---------------------------------------------------------------------------
// K3: bucket-ordered edge pass, 8 lanes per TWO consecutive edges.
//   All 6 gather/rec loads issued up front -> 2x memory-level parallelism.
// ---------------------------------------------------------------------------
__global__ __launch_bounds__(256) void k3_edge()
{
    int t = blockIdx.x * 256 + threadIdx.x;
    int g   = t >> 3;                 // group handles edges 2g, 2g+1
    int sub = t & 7;
    int s = sub & 3;

    uint4 rc0 = __ldg(g_rec + 2 * g);
    uint4 rc1 = __ldg(g_rec + 2 * g + 1);

    // edge 0 setup
    float p00 = __uint_as_float(rc0.z) * 4.f;
    float p01 = __uint_as_float(rc0.w) * 4.f;
    float fl00 = floorf(p00), fl01 = floorf(p01);
    float fr00 = p00 - fl00,  fr01 = p01 - fl01;
    int w00 = (int)fl00 + 5 * (int)fl01;
    const char* base0 = (const char*)g_xwp + (size_t)rc0.y * 1600 + (sub << 4);

    // edge 1 setup
    float p10 = __uint_as_float(rc1.z) * 4.f;
    float p11 = __uint_as_float(rc1.w) * 4.f;
    float fl10 = floorf(p10), fl11 = floorf(p11);
    float fr10 = p10 - fl10,  fr11 = p11 - fl11;
    int w10 = (int)fl10 + 5 * (int)fl11;
    const char* base1 = (const char*)g_xwp + (size_t)rc1.y * 1600 + (sub << 4);

    // issue all 4 tap-pair gathers before any math (MLP)
    uint4 qa0 = __ldg((const uint4*)(base0 + w00 * 64));
    uint4 qb0 = __ldg((const uint4*)(base0 + (w00 + 5) * 64));
    uint4 qa1 = __ldg((const uint4*)(base1 + w10 * 64));
    uint4 qb1 = __ldg((const uint4*)(base1 + (w10 + 5) * 64));

    float4 A0 = __ldg(((const float4*)g_att2p) + 2 * s);
    float4 A1 = __ldg(((const float4*)g_att2p) + 2 * s + 1);

    // ---------------- edge 0 ----------------
    {
        int row = (int)rc0.x;
        float fa = (sub & 4) ? fr00 : (1.f - fr00);
        unsigned ua = h2b(fa * (1.f - fr01), fa * (1.f - fr01));
        unsigned ub = h2b(fa * fr01,         fa * fr01);
        __half2 ha = *(__half2*)&ua, hb = *(__half2*)&ub;

        __half2 h0 = __hmul2(ha, *(__half2*)&qa0.x);
        __half2 h1 = __hmul2(ha, *(__half2*)&qa0.y);
        __half2 h2 = __hmul2(ha, *(__half2*)&qa0.z);
        __half2 h3 = __hmul2(ha, *(__half2*)&qa0.w);
        h0 = __hfma2(hb, *(__half2*)&qb0.x, h0);
        h1 = __hfma2(hb, *(__half2*)&qb0.y, h1);
        h2 = __hfma2(hb, *(__half2*)&qb0.z, h2);
        h3 = __hfma2(hb, *(__half2*)&qb0.w, h3);

        unsigned uu;
        uu = __shfl_xor_sync(0xffffffffu, *(unsigned*)&h0, 4);
        h0 = __hadd2(h0, *(__half2*)&uu);
        uu = __shfl_xor_sync(0xffffffffu, *(unsigned*)&h1, 4);
        h1 = __hadd2(h1, *(__half2*)&uu);
        uu = __shfl_xor_sync(0xffffffffu, *(unsigned*)&h2, 4);
        h2 = __hadd2(h2, *(__half2*)&uu);
        uu = __shfl_xor_sync(0xffffffffu, *(unsigned*)&h3, 4);
        h3 = __hadd2(h3, *(__half2*)&uu);

        float2 f0 = __half22float2(h0), f1 = __half22float2(h1);
        float2 f2 = __half22float2(h2), f3 = __half22float2(h3);

        float d = f0.x*A0.x + f0.y*A0.y + f1.x*A0.z + f1.y*A0.w
                + f2.x*A1.x + f2.y*A1.y + f3.x*A1.z + f3.y*A1.w;
        d += __shfl_xor_sync(0xffffffffu, d, 1);
        d += __shfl_xor_sync(0xffffffffu, d, 2);

        float alpha = d + __ldg(g_rdot + row);
        alpha = (alpha > 0.f) ? alpha : 0.2f * alpha;
        float ex = __expf(alpha);

        if (sub == 0) atomicAdd(g_denom + row, ex);

        float* ap = g_acc + (size_t)row * 32 + s * 8 + (sub & 4);
        float4 wv = (sub & 4)
            ? make_float4(f2.x * ex, f2.y * ex, f3.x * ex, f3.y * ex)
            : make_float4(f0.x * ex, f0.y * ex, f1.x * ex, f1.y * ex);
        asm volatile("red.global.add.v4.f32 [%0], {%1,%2,%3,%4};"
                     :: "l"(ap), "f"(wv.x), "f"(wv.y), "f"(wv.z), "f"(wv.w)
                     : "memory");
    }

    // ---------------- edge 1 ----------------
    {
        int row = (int)rc1.x;
        float fa = (sub & 4) ? fr10 : (1.f - fr10);
        unsigned ua = h2b(fa * (1.f - fr11), fa * (1.f - fr11));
        unsigned ub = h2b(fa * fr11,         fa * fr11);
        __half2 ha = *(__half2*)&ua, hb = *(__half2*)&ub;

        __half2 h0 = __hmul2(ha, *(__half2*)&qa1.x);
        __half2 h1 = __hmul2(ha, *(__half2*)&qa1.y);
        __half2 h2 = __hmul2(ha, *(__half2*)&qa1.z);
        __half2 h3 = __hmul2(ha, *(__half2*)&qa1.w);
        h0 = __hfma2(hb, *(__half2*)&qb1.x, h0);
        h1 = __hfma2(hb, *(__half2*)&qb1.y, h1);
        h2 = __hfma2(hb, *(__half2*)&qb1.z, h2);
        h3 = __hfma2(hb, *(__half2*)&qb1.w, h3);

        unsigned uu;
        uu = __shfl_xor_sync(0xffffffffu, *(unsigned*)&h0, 4);
        h0 = __hadd2(h0, *(__half2*)&uu);
        uu = __shfl_xor_sync(0xffffffffu, *(unsigned*)&h1, 4);
        h1 = __hadd2(h1, *(__half2*)&uu);
        uu = __shfl_xor_sync(0xffffffffu, *(unsigned*)&h2, 4);
        h2 = __hadd2(h2, *(__half2*)&uu);
        uu = __shfl_xor_sync(0xffffffffu, *(unsigned*)&h3, 4);
        h3 = __hadd2(h3, *(__half2*)&uu);

        float2 f0 = __half22float2(h0), f1 = __half22float2(h1);
        float2 f2 = __half22float2(h2), f3 = __half22float2(h3);

        float d = f0.x*A0.x + f0.y*A0.y + f1.x*A0.z + f1.y*A0.w
                + f2.x*A1.x + f2.y*A1.y + f3.x*A1.z + f3.y*A1.w;
        d += __shfl_xor_sync(0xffffffffu, d, 1);
        d += __shfl_xor_sync(0xffffffffu, d, 2);

        float alpha = d + __ldg(g_rdot + row);
        alpha = (alpha > 0.f) ? alpha : 0.2f * alpha;
        float ex = __expf(alpha);

        if (sub == 0) atomicAdd(g_denom + row, ex);

        float* ap = g_acc + (size_t)row * 32 + s * 8 + (sub & 4);
        float4 wv = (sub & 4)
            ? make_float4(f2.x * ex, f2.y * ex, f3.x * ex, f3.y * ex)
            : make_float4(f0.x * ex, f0.y * ex, f1.x * ex, f1.y * ex);
        asm volatile("red.global.add.v4.f32 [%0], {%1,%2,%3,%4};"
                     :: "l"(ap), "f"(wv.x), "f"(wv.y), "f"(wv.z), "f"(wv.w)
                     : "memory");
    }
}

// ---------------------------------------------------------------------------
// K4: out = unpermute( acc/(denom+1e-16) + x_root_perm + bias_perm )
//     + restore g_bcnt=0 invariant for the next launch
// ---------------------------------------------------------------------------
__global__ __launch_bounds__(256) void k4_out(float* __restrict__ out)
{
    if (blockIdx.x == 0 && threadIdx.x < NBUK) g_bcnt[threadIdx.x] = 0;

    int i = blockIdx.x * 256 + threadIdx.x;     // 800000 = NN*8
    int n = i >> 3, g = i & 7;
    float r = 1.f / (g_denom[n] + 1e-16f);
    const float* ap  = g_acc + (size_t)n * 32;
    const float* xp_ = g_xrb + (size_t)n * 32;
    int h  = (g >> 2) & 1;
    int bb = (g >> 1) & 1;
    int pos0 = 8 * ((2 * g) & 3)     + 4 * h + 2 * bb;
    int pos1 = 8 * ((2 * g + 1) & 3) + 4 * h + 2 * bb;
    float2 u0 = *(const float2*)(ap + pos0);
    float2 u1 = *(const float2*)(ap + pos1);
    float2 x0 = *(const float2*)(xp_ + pos0);
    float2 x1 = *(const float2*)(xp_ + pos1);
    float2 b0 = *(const float2*)(g_biasp + pos0);
    float2 b1 = *(const float2*)(g_biasp + pos1);
    float4 o;
    o.x = fmaf(u0.x, r, x0.x + b0.x);
    o.y = fmaf(u0.y, r, x0.y + b0.y);
    o.z = fmaf(u1.x, r, x1.x + b1.x);
    o.w = fmaf(u1.y, r, x1.y + b1.y);
    ((float4*)out)[i] = o;
}

extern "C" void kernel_launch(void* const* d_in, const int* in_sizes, int n_in,
                              void* d_out, int out_size)
{
    const float* x      = (const float*)d_in[0];
    const int*   ei     = (const int*)d_in[1];
    const float* pseudo = (const float*)d_in[2];
    const float* W      = (const float*)d_in[3];
    const float* rootW  = (const float*)d_in[4];
    const float* attW   = (const float*)d_in[5];
    const float* bias   = (const float*)d_in[6];
    float* out = (float*)d_out;

    static cudaStream_t s_side = nullptr;
    static cudaEvent_t evF = nullptr, evJ = nullptr;
    if (!s_side) {
        cudaFuncSetAttribute(k2_mma,
            cudaFuncAttributeMaxDynamicSharedMemorySize, 61440);
        cudaStreamCreateWithFlags(&s_side, cudaStreamNonBlocking);
        cudaEventCreateWithFlags(&evF, cudaEventDisableTiming);
        cudaEventCreateWithFlags(&evJ, cudaEventDisableTiming);
    }

    // fork: sort chain + tables on side stream (depends only on ei/pseudo/attW/bias)
    cudaEventRecord(evF, 0);
    cudaStreamWaitEvent(s_side, evF, 0);
    s1_hist<<<625, 256, 0, s_side>>>(ei);
    s2_scan<<<1, 128, 0, s_side>>>(attW, bias);
    s3_scat<<<625, 256, 0, s_side>>>(ei, pseudo);
    cudaEventRecord(evJ, s_side);

    // main chain: node-side work (depends only on x/W/attW)
    k1_conv<<<3125, 256>>>(x);
    k2_mma <<<NNP / 128, 256, 61440>>>(W, rootW, attW);

    // join, then edge pass + epilogue
    cudaStreamWaitEvent(0, evJ, 0);
    k3_edge<<<(NE * 4) / 256, 256>>>();
    k4_out <<<3125, 256>>>(out);
}